// round 1
// baseline (speedup 1.0000x reference)
#include <cuda_runtime.h>

// Problem constants: B=4, C=64, H=128, W=128, N=16, R=4, P=36
#define NPLANES (4*64)          // b*c planes
#define PLANE   (128*128)
#define TOTAL   (4*64*128*128)

__device__ float g_xT[TOTAL];   // x transposed (h<->w) per plane
__device__ float g_yT[TOTAL];   // vertical-direction output, transposed layout

__device__ __forceinline__ float ex2f(float v) {
    float r; asm("ex2.approx.ftz.f32 %0, %1;" : "=f"(r) : "f"(v)); return r;
}

// ---------------- smem layout (floats) ----------------
#define OFF_U   0                    // u / (delta*u)  [64][132]  c-major
#define OFF_DL  (OFF_U + 64*132)     // delta          [128][65]
#define OFF_Y   (OFF_DL + 128*65)    // y accum        [128][65]
#define OFF_Bm  (OFF_Y + 128*65)     // B              [128][16]
#define OFF_Cm  (OFF_Bm + 128*16)    // C              [128][16]
#define OFF_DT  (OFF_Cm + 128*16)    // dt_raw         [128][4]
#define OFF_W   (OFF_DT + 128*4)     // x_proj_w       [64][40]  c-major
#define OFF_DTW (OFF_W + 64*40)      // dt_proj_w      [64][4]
#define OFF_DTB (OFF_DTW + 64*4)     // dt_proj_b      [64]
#define OFF_DD  (OFF_DTB + 64)       // D              [64]
#define SMEM_FLOATS (OFF_DD + 64)
#define SMEM_BYTES  (SMEM_FLOATS * 4)

// ---------------- transpose x -> g_xT ----------------
__global__ void transpose_kernel(const float* __restrict__ x) {
    __shared__ float tile[32][33];
    int plane = blockIdx.z;
    const float* src = x + plane * PLANE;
    float* dst = g_xT + plane * PLANE;
    int h0 = blockIdx.x * 32, w0 = blockIdx.y * 32;
    int tx = threadIdx.x, ty = threadIdx.y;
#pragma unroll
    for (int j = 0; j < 32; j += 8)
        tile[ty + j][tx] = src[(h0 + ty + j) * 128 + (w0 + tx)];
    __syncthreads();
#pragma unroll
    for (int j = 0; j < 32; j += 8)
        dst[(w0 + ty + j) * 128 + (h0 + tx)] = tile[tx][ty + j];
}

// ---------------- out += transpose(g_yT) ----------------
__global__ void addT_kernel(float* __restrict__ out) {
    __shared__ float tile[32][33];
    int plane = blockIdx.z;
    const float* src = g_yT + plane * PLANE;  // [w][h]
    float* dst = out + plane * PLANE;         // [h][w]
    int h0 = blockIdx.x * 32, w0 = blockIdx.y * 32;
    int tx = threadIdx.x, ty = threadIdx.y;
#pragma unroll
    for (int j = 0; j < 32; j += 8)
        tile[ty + j][tx] = src[(w0 + ty + j) * 128 + (h0 + tx)];
    __syncthreads();
#pragma unroll
    for (int j = 0; j < 32; j += 8)
        dst[(h0 + ty + j) * 128 + (w0 + tx)] += tile[tx][ty + j];
}

// ---------------- fused proj + delta + selective scan ----------------
__global__ void __launch_bounds__(256, 1)
mamba_kernel(const float* __restrict__ x,
             const float* __restrict__ A_log,
             const float* __restrict__ Dvec,
             const float* __restrict__ x_proj_w,
             const float* __restrict__ dt_proj_w,
             const float* __restrict__ dt_proj_b,
             float* __restrict__ out)
{
    extern __shared__ float sm[];
    float* s_u   = sm + OFF_U;
    float* s_dl  = sm + OFF_DL;
    float* s_y   = sm + OFF_Y;
    float* s_B   = sm + OFF_Bm;
    float* s_C   = sm + OFF_Cm;
    float* s_dt  = sm + OFF_DT;
    float* s_W   = sm + OFF_W;
    float* s_dtw = sm + OFF_DTW;
    float* s_dtb = sm + OFF_DTB;
    float* s_D   = sm + OFF_DD;

    const int tid = threadIdx.x;
    const int sidx = blockIdx.x;
    const int dir = sidx >> 9;        // 0: horizontal, 1: vertical
    const int sq  = sidx & 511;
    const int b   = sq >> 7;
    const int row = sq & 127;
    const float* in = dir ? g_xT : x;
    float* op       = dir ? g_yT : out;
    const int base = (b * 64 * 128 + row) * 128;   // + c*16384 + l

    const int d  = tid >> 2;   // channel for scan phase
    const int nb = tid & 3;    // state quad
    float A2r[4];
#pragma unroll
    for (int i = 0; i < 4; i++)
        A2r[i] = -__expf(A_log[d * 16 + nb * 4 + i]) * 1.4426950408889634f;

    // ---- load weights ----
    for (int idx = tid; idx < 36 * 64; idx += 256) {
        int p = idx >> 6, c = idx & 63;
        s_W[c * 40 + p] = x_proj_w[idx];       // c-major
    }
    s_dtw[tid] = dt_proj_w[tid];               // 256 elements
    if (tid < 64) { s_dtb[tid] = dt_proj_b[tid]; s_D[tid] = Dvec[tid]; }

    // ---- load u tile: [64 c][128 l], coalesced float4 ----
    for (int idx = tid; idx < 2048; idx += 256) {
        int c = idx >> 5, l4 = (idx & 31) * 4;
        float4 v = *reinterpret_cast<const float4*>(in + base + c * 16384 + l4);
        *reinterpret_cast<float4*>(&s_u[c * 132 + l4]) = v;
    }
    __syncthreads();

    // ---- proj = u @ x_proj_w^T : register tiles 2l x 4p, 64x9 = 576 tiles ----
    for (int tile = tid; tile < 576; tile += 256) {
        int lg = tile / 9, pg = tile % 9;
        int l0 = lg * 2, p0 = pg * 4;
        float a00 = 0.f, a01 = 0.f, a02 = 0.f, a03 = 0.f;
        float a10 = 0.f, a11 = 0.f, a12 = 0.f, a13 = 0.f;
#pragma unroll 4
        for (int c = 0; c < 64; c++) {
            float2 uv = *reinterpret_cast<const float2*>(&s_u[c * 132 + l0]);
            float4 wv = *reinterpret_cast<const float4*>(&s_W[c * 40 + p0]);
            a00 = fmaf(uv.x, wv.x, a00); a01 = fmaf(uv.x, wv.y, a01);
            a02 = fmaf(uv.x, wv.z, a02); a03 = fmaf(uv.x, wv.w, a03);
            a10 = fmaf(uv.y, wv.x, a10); a11 = fmaf(uv.y, wv.y, a11);
            a12 = fmaf(uv.y, wv.z, a12); a13 = fmaf(uv.y, wv.w, a13);
        }
        if (pg == 0) {
            *reinterpret_cast<float4*>(&s_dt[(l0 + 0) * 4]) = make_float4(a00, a01, a02, a03);
            *reinterpret_cast<float4*>(&s_dt[(l0 + 1) * 4]) = make_float4(a10, a11, a12, a13);
        } else if (pg < 5) {
            int n0 = p0 - 4;
            *reinterpret_cast<float4*>(&s_B[(l0 + 0) * 16 + n0]) = make_float4(a00, a01, a02, a03);
            *reinterpret_cast<float4*>(&s_B[(l0 + 1) * 16 + n0]) = make_float4(a10, a11, a12, a13);
        } else {
            int n0 = p0 - 20;
            *reinterpret_cast<float4*>(&s_C[(l0 + 0) * 16 + n0]) = make_float4(a00, a01, a02, a03);
            *reinterpret_cast<float4*>(&s_C[(l0 + 1) * 16 + n0]) = make_float4(a10, a11, a12, a13);
        }
    }
    __syncthreads();

    // ---- delta = softplus(dt_raw @ dtw^T + b); y init = u*D; u <- delta*u ----
    for (int idx = tid; idx < 8192; idx += 256) {
        int l = idx >> 6, dd = idx & 63;
        float4 dt4 = *reinterpret_cast<const float4*>(&s_dt[l * 4]);
        float4 w4  = *reinterpret_cast<const float4*>(&s_dtw[dd * 4]);
        float raw = s_dtb[dd];
        raw = fmaf(dt4.x, w4.x, raw);
        raw = fmaf(dt4.y, w4.y, raw);
        raw = fmaf(dt4.z, w4.z, raw);
        raw = fmaf(dt4.w, w4.w, raw);
        float sp = (raw > 15.0f) ? raw : log1pf(__expf(raw));
        float uu = s_u[dd * 132 + l];
        s_dl[l * 65 + dd] = sp;
        s_y[l * 65 + dd]  = uu * s_D[dd];
        s_u[dd * 132 + l] = sp * uu;     // now holds delta*u
    }
    __syncthreads();

    // ---- selective scan: thread = (channel d, 4 states) ----
    {
        float h0 = 0.f, h1 = 0.f, h2 = 0.f, h3 = 0.f;
        const float* durow = s_u + d * 132;
#pragma unroll 4
        for (int l = 0; l < 128; l++) {
            float dl = s_dl[l * 65 + d];
            float du = durow[l];
            float4 b4 = *reinterpret_cast<const float4*>(&s_B[l * 16 + nb * 4]);
            float4 c4 = *reinterpret_cast<const float4*>(&s_C[l * 16 + nb * 4]);
            h0 = fmaf(ex2f(dl * A2r[0]), h0, du * b4.x);
            h1 = fmaf(ex2f(dl * A2r[1]), h1, du * b4.y);
            h2 = fmaf(ex2f(dl * A2r[2]), h2, du * b4.z);
            h3 = fmaf(ex2f(dl * A2r[3]), h3, du * b4.w);
            float t = fmaf(h0, c4.x, fmaf(h1, c4.y, fmaf(h2, c4.z, h3 * c4.w)));
            t += __shfl_xor_sync(0xffffffffu, t, 1);
            t += __shfl_xor_sync(0xffffffffu, t, 2);
            if (nb == 0) s_y[l * 65 + d] += t;
        }
    }
    __syncthreads();

    // ---- coalesced writeout ----
    for (int idx = tid; idx < 2048; idx += 256) {
        int c = idx >> 5, l4 = (idx & 31) * 4;
        float4 v;
        v.x = s_y[(l4 + 0) * 65 + c];
        v.y = s_y[(l4 + 1) * 65 + c];
        v.z = s_y[(l4 + 2) * 65 + c];
        v.w = s_y[(l4 + 3) * 65 + c];
        *reinterpret_cast<float4*>(op + base + c * 16384 + l4) = v;
    }
}

extern "C" void kernel_launch(void* const* d_in, const int* in_sizes, int n_in,
                              void* d_out, int out_size) {
    const float* x     = (const float*)d_in[0];
    const float* A_log = (const float*)d_in[1];
    const float* Dv    = (const float*)d_in[2];
    const float* xpw   = (const float*)d_in[3];
    const float* dtw   = (const float*)d_in[4];
    const float* dtb   = (const float*)d_in[5];
    float* out = (float*)d_out;

    cudaFuncSetAttribute(mamba_kernel, cudaFuncAttributeMaxDynamicSharedMemorySize, SMEM_BYTES);

    dim3 tb(32, 8);
    dim3 tg(4, 4, NPLANES);
    transpose_kernel<<<tg, tb>>>(x);
    mamba_kernel<<<1024, 256, SMEM_BYTES>>>(x, A_log, Dv, xpw, dtw, dtb, out);
    addT_kernel<<<tg, tb>>>(out);
}

// round 2
// speedup vs baseline: 1.4153x; 1.4153x over previous
#include <cuda_runtime.h>

// Problem: B=4, C=64, H=128, W=128, N=16, R=4, P=36
#define NPLANES (4*64)
#define PLANE   (128*128)
#define TOTAL   (4*64*128*128)
#define LOG2E   1.4426950408889634f

__device__ float g_xT[TOTAL];   // x transposed (h<->w) per plane
__device__ float g_yT[TOTAL];   // vertical-direction output, transposed layout

__device__ __forceinline__ float ex2f(float v) {
    float r; asm("ex2.approx.ftz.f32 %0, %1;" : "=f"(r) : "f"(v)); return r;
}

// ---------------- smem layout (floats), total 24320 f = 97280 B ----------------
#define OFF_U   0                    // u -> delta*u   [64][132]  c-major
#define OFF_DL  (OFF_U + 64*132)     // delta -> y     [128][65]  l-major
#define OFF_Bm  (OFF_DL + 128*65)    // B              [128][16]
#define OFF_Cm  (OFF_Bm + 128*16)    // C              [128][16]
#define OFF_DT  (OFF_Cm + 128*16)    // dt_raw         [128][4]
#define OFF_W   (OFF_DT + 128*4)     // x_proj_w       [64][40]  c-major
#define OFF_DTW (OFF_W + 64*40)      // dt_proj_w      [64][4]
#define OFF_DTB (OFF_DTW + 64*4)     // dt_proj_b      [64]
#define OFF_DD  (OFF_DTB + 64)       // D              [64]
#define SMEM_FLOATS (OFF_DD + 64)
#define SMEM_BYTES  (SMEM_FLOATS * 4)

// ---------------- transpose x -> g_xT ----------------
__global__ void transpose_kernel(const float* __restrict__ x) {
    __shared__ float tile[32][33];
    int plane = blockIdx.z;
    const float* src = x + plane * PLANE;
    float* dst = g_xT + plane * PLANE;
    int h0 = blockIdx.x * 32, w0 = blockIdx.y * 32;
    int tx = threadIdx.x, ty = threadIdx.y;
#pragma unroll
    for (int j = 0; j < 32; j += 8)
        tile[ty + j][tx] = src[(h0 + ty + j) * 128 + (w0 + tx)];
    __syncthreads();
#pragma unroll
    for (int j = 0; j < 32; j += 8)
        dst[(w0 + ty + j) * 128 + (h0 + tx)] = tile[tx][ty + j];
}

// ---------------- out += transpose(g_yT) ----------------
__global__ void addT_kernel(float* __restrict__ out) {
    __shared__ float tile[32][33];
    int plane = blockIdx.z;
    const float* src = g_yT + plane * PLANE;  // [w][h]
    float* dst = out + plane * PLANE;         // [h][w]
    int h0 = blockIdx.x * 32, w0 = blockIdx.y * 32;
    int tx = threadIdx.x, ty = threadIdx.y;
#pragma unroll
    for (int j = 0; j < 32; j += 8)
        tile[ty + j][tx] = src[(w0 + ty + j) * 128 + (h0 + tx)];
    __syncthreads();
#pragma unroll
    for (int j = 0; j < 32; j += 8)
        dst[(h0 + ty + j) * 128 + (w0 + tx)] += tile[tx][ty + j];
}

// ---------------- fused proj + delta + selective scan (1 seq / 128-thread CTA) ----------------
__global__ void __launch_bounds__(128, 2)
mamba_kernel(const float* __restrict__ x,
             const float* __restrict__ A_log,
             const float* __restrict__ Dvec,
             const float* __restrict__ x_proj_w,
             const float* __restrict__ dt_proj_w,
             const float* __restrict__ dt_proj_b,
             float* __restrict__ out)
{
    extern __shared__ float sm[];
    float* s_u   = sm + OFF_U;
    float* s_dl  = sm + OFF_DL;   // delta, later overwritten with y
    float* s_B   = sm + OFF_Bm;
    float* s_C   = sm + OFF_Cm;
    float* s_dt  = sm + OFF_DT;
    float* s_W   = sm + OFF_W;
    float* s_dtw = sm + OFF_DTW;
    float* s_dtb = sm + OFF_DTB;
    float* s_D   = sm + OFF_DD;

    const int tid = threadIdx.x;
    const int sidx = blockIdx.x;
    const int dir = sidx >> 9;        // 0: horizontal, 1: vertical
    const int sq  = sidx & 511;
    const int b   = sq >> 7;
    const int row = sq & 127;
    const float* in = dir ? g_xT : x;
    float* op       = dir ? g_yT : out;
    const int base = (b * 64 * 128 + row) * 128;   // + c*16384 + l

    // scan mapping: thread = (channel d, 8 states)
    const int d    = tid >> 1;
    const int half = tid & 1;
    const int n0   = half * 8;
    float A2[8];
#pragma unroll
    for (int j = 0; j < 8; j++)
        A2[j] = -__expf(__ldg(&A_log[d * 16 + n0 + j])) * LOG2E;

    // ---- load weights ----
    for (int idx = tid; idx < 36 * 64; idx += 128) {
        int p = idx >> 6, c = idx & 63;
        s_W[c * 40 + p] = x_proj_w[idx];       // c-major
    }
    s_dtw[tid] = dt_proj_w[tid];
    s_dtw[tid + 128] = dt_proj_w[tid + 128];
    if (tid < 64) { s_dtb[tid] = dt_proj_b[tid]; s_D[tid] = Dvec[tid]; }

    // ---- load u tile: [64 c][128 l], coalesced float4 ----
    for (int k = 0; k < 16; k++) {
        int idx = k * 128 + tid;
        int c = idx >> 5, l4 = (idx & 31) * 4;
        float4 v = *reinterpret_cast<const float4*>(in + base + c * 16384 + l4);
        *reinterpret_cast<float4*>(&s_u[c * 132 + l4]) = v;
    }
    __syncthreads();

    // ---- proj = u @ x_proj_w^T : register tiles 4l x 4p, 32x9 = 288 tiles ----
    for (int tile = tid; tile < 288; tile += 128) {
        int lg = tile / 9, pg = tile % 9;
        int l0 = lg * 4, p0 = pg * 4;
        float a[4][4];
#pragma unroll
        for (int i = 0; i < 4; i++)
#pragma unroll
            for (int j = 0; j < 4; j++) a[i][j] = 0.f;
#pragma unroll 4
        for (int c = 0; c < 64; c++) {
            float4 uv = *reinterpret_cast<const float4*>(&s_u[c * 132 + l0]);
            float4 wv = *reinterpret_cast<const float4*>(&s_W[c * 40 + p0]);
            float uu[4] = {uv.x, uv.y, uv.z, uv.w};
            float ww[4] = {wv.x, wv.y, wv.z, wv.w};
#pragma unroll
            for (int i = 0; i < 4; i++)
#pragma unroll
                for (int j = 0; j < 4; j++)
                    a[i][j] = fmaf(uu[i], ww[j], a[i][j]);
        }
        if (pg == 0) {
#pragma unroll
            for (int i = 0; i < 4; i++)
                *reinterpret_cast<float4*>(&s_dt[(l0 + i) * 4]) =
                    make_float4(a[i][0], a[i][1], a[i][2], a[i][3]);
        } else if (pg < 5) {
            int nn = p0 - 4;
#pragma unroll
            for (int i = 0; i < 4; i++)
                *reinterpret_cast<float4*>(&s_B[(l0 + i) * 16 + nn]) =
                    make_float4(a[i][0], a[i][1], a[i][2], a[i][3]);
        } else {
            int nn = p0 - 20;
#pragma unroll
            for (int i = 0; i < 4; i++)
                *reinterpret_cast<float4*>(&s_C[(l0 + i) * 16 + nn]) =
                    make_float4(a[i][0], a[i][1], a[i][2], a[i][3]);
        }
    }
    __syncthreads();

    // ---- delta = softplus(dt_raw @ dtw^T + b); u <- delta*u ----
    for (int k = 0; k < 64; k++) {
        int idx = k * 128 + tid;
        int l = idx >> 6, dd = idx & 63;
        float4 dt4 = *reinterpret_cast<const float4*>(&s_dt[l * 4]);
        float4 w4  = *reinterpret_cast<const float4*>(&s_dtw[dd * 4]);
        float raw = s_dtb[dd];
        raw = fmaf(dt4.x, w4.x, raw);
        raw = fmaf(dt4.y, w4.y, raw);
        raw = fmaf(dt4.z, w4.z, raw);
        raw = fmaf(dt4.w, w4.w, raw);
        float sp = (raw > 20.0f) ? raw : __logf(1.0f + __expf(raw));
        float uu = s_u[dd * 132 + l];
        s_dl[l * 65 + dd] = sp;
        s_u[dd * 132 + l] = sp * uu;     // now holds delta*u
    }
    __syncthreads();

    // ---- selective scan: 8 states per thread, y overwrites delta slot ----
    {
        float h0 = 0.f, h1 = 0.f, h2 = 0.f, h3 = 0.f;
        float h4 = 0.f, h5 = 0.f, h6 = 0.f, h7 = 0.f;
        const float* durow = s_u + d * 132;
#pragma unroll 4
        for (int l = 0; l < 128; l++) {
            float dl = s_dl[l * 65 + d];
            float du = durow[l];
            float4 b0 = *reinterpret_cast<const float4*>(&s_B[l * 16 + n0]);
            float4 b1 = *reinterpret_cast<const float4*>(&s_B[l * 16 + n0 + 4]);
            float4 c0 = *reinterpret_cast<const float4*>(&s_C[l * 16 + n0]);
            float4 c1 = *reinterpret_cast<const float4*>(&s_C[l * 16 + n0 + 4]);
            h0 = fmaf(ex2f(dl * A2[0]), h0, du * b0.x);
            h1 = fmaf(ex2f(dl * A2[1]), h1, du * b0.y);
            h2 = fmaf(ex2f(dl * A2[2]), h2, du * b0.z);
            h3 = fmaf(ex2f(dl * A2[3]), h3, du * b0.w);
            h4 = fmaf(ex2f(dl * A2[4]), h4, du * b1.x);
            h5 = fmaf(ex2f(dl * A2[5]), h5, du * b1.y);
            h6 = fmaf(ex2f(dl * A2[6]), h6, du * b1.z);
            h7 = fmaf(ex2f(dl * A2[7]), h7, du * b1.w);
            float t = fmaf(h0, c0.x, fmaf(h1, c0.y, fmaf(h2, c0.z, h3 * c0.w)));
            t = fmaf(h4, c1.x, fmaf(h5, c1.y, fmaf(h6, c1.z, fmaf(h7, c1.w, t))));
            t += __shfl_xor_sync(0xffffffffu, t, 1);
            if (half == 0) s_dl[l * 65 + d] = t;   // y replaces delta
        }
    }
    __syncthreads();

    // ---- coalesced writeout: y + u*D (u re-read from global, L2-hot) ----
    for (int k = 0; k < 16; k++) {
        int idx = k * 128 + tid;
        int c = idx >> 5, l4 = (idx & 31) * 4;
        float Dc = s_D[c];
        float4 uv = *reinterpret_cast<const float4*>(in + base + c * 16384 + l4);
        float4 v;
        v.x = fmaf(uv.x, Dc, s_dl[(l4 + 0) * 65 + c]);
        v.y = fmaf(uv.y, Dc, s_dl[(l4 + 1) * 65 + c]);
        v.z = fmaf(uv.z, Dc, s_dl[(l4 + 2) * 65 + c]);
        v.w = fmaf(uv.w, Dc, s_dl[(l4 + 3) * 65 + c]);
        *reinterpret_cast<float4*>(op + base + c * 16384 + l4) = v;
    }
}

extern "C" void kernel_launch(void* const* d_in, const int* in_sizes, int n_in,
                              void* d_out, int out_size) {
    const float* x     = (const float*)d_in[0];
    const float* A_log = (const float*)d_in[1];
    const float* Dv    = (const float*)d_in[2];
    const float* xpw   = (const float*)d_in[3];
    const float* dtw   = (const float*)d_in[4];
    const float* dtb   = (const float*)d_in[5];
    float* out = (float*)d_out;

    cudaFuncSetAttribute(mamba_kernel, cudaFuncAttributeMaxDynamicSharedMemorySize, SMEM_BYTES);

    dim3 tb(32, 8);
    dim3 tg(4, 4, NPLANES);
    transpose_kernel<<<tg, tb>>>(x);
    mamba_kernel<<<1024, 128, SMEM_BYTES>>>(x, A_log, Dv, xpw, dtw, dtb, out);
    addT_kernel<<<tg, tb>>>(out);
}